// round 6
// baseline (speedup 1.0000x reference)
#include <cuda_runtime.h>

#define NUSER 50000
#define NITEM 100000
#define NN    150000
#define DD    64
#define EE    2400000

// scratch: static device globals (no runtime allocation allowed)
__device__ float g_ego[NN * DD];   // 38.4 MB
__device__ float g_side[NN * DD];  // 38.4 MB

// tiny shim so ncu (-s 5 -c 1) lands on a layer_kernel launch
__global__ void prof_shim_kernel() {}

// ---------------------------------------------------------------------------
// init: ego = concat(user_emb, item_emb); side = 0; out[:, 0:64] = ego (raw)
// ---------------------------------------------------------------------------
__global__ void init_kernel(const float* __restrict__ ue,
                            const float* __restrict__ ie,
                            float* __restrict__ out) {
    int i4 = blockIdx.x * blockDim.x + threadIdx.x;  // float4 index
    if (i4 >= NN * 16) return;
    int row = i4 >> 4;
    int q   = i4 & 15;
    float4 v;
    if (row < NUSER) v = reinterpret_cast<const float4*>(ue)[i4];
    else             v = reinterpret_cast<const float4*>(ie)[i4 - NUSER * 16];
    reinterpret_cast<float4*>(g_ego)[i4]  = v;
    reinterpret_cast<float4*>(g_side)[i4] = make_float4(0.f, 0.f, 0.f, 0.f);
    reinterpret_cast<float4*>(out)[row * 64 + q] = v;
}

// ---------------------------------------------------------------------------
// SpMM: side[r] += vals[e] * ego[c].  4 threads/edge, each owns 4 float4s
// (MLP=4: all 4 gathers issued before the 4 REDs).
// ---------------------------------------------------------------------------
__global__ void spmm_kernel(const float* __restrict__ vals,
                            const int*   __restrict__ rows,
                            const int*   __restrict__ cols) {
    int t = blockIdx.x * blockDim.x + threadIdx.x;  // EE*4 = 9.6M
    if (t >= EE * 4) return;
    int e = t >> 2;
    int q = t & 3;
    int c   = __ldg(cols + e);
    int r   = __ldg(rows + e);
    float v = __ldg(vals + e);
    const float4* src = reinterpret_cast<const float4*>(g_ego + (size_t)c * DD) + q;
    float4*       dst = reinterpret_cast<float4*>(g_side + (size_t)r * DD) + q;

    float4 x[4];
#pragma unroll
    for (int j = 0; j < 4; j++) x[j] = __ldg(src + j * 4);   // independent: MLP=4
#pragma unroll
    for (int j = 0; j < 4; j++) {
        x[j].x *= v; x[j].y *= v; x[j].z *= v; x[j].w *= v;
#if __CUDA_ARCH__ >= 900
        atomicAdd(dst + j * 4, x[j]);
#else
        float* p = reinterpret_cast<float*>(dst + j * 4);
        atomicAdd(p + 0, x[j].x); atomicAdd(p + 1, x[j].y);
        atomicAdd(p + 2, x[j].z); atomicAdd(p + 3, x[j].w);
#endif
    }
}

// ---------------------------------------------------------------------------
// Fused dense layer, register-tiled:
//   Block = 512 threads (16 tx x 32 ty), tile = 64 rows x 64 cols,
//   thread = 2 rows x 4 cols (both GEMMs).
//   sum = leaky(side@Wg+bg); bi = leaky((ego*side)@Wb+bb); ego = sum+bi
//   out[:, koff:+64] = l2norm(ego); side cleared during staging.
// smem 64KB, 2 blocks/SM -> 32 warps/SM (2x R4's warp parallelism).
// ---------------------------------------------------------------------------
__global__ __launch_bounds__(512, 2) void layer_kernel(
    const float* __restrict__ Wg, const float* __restrict__ bg,
    const float* __restrict__ Wb, const float* __restrict__ bb,
    float* __restrict__ out, int koff) {
    __shared__ float sWg[64 * 64];
    __shared__ float sWb[64 * 64];
    __shared__ float sS [64 * 64];
    __shared__ float sES[64 * 64];

    int tid = threadIdx.x;
    // stage weights (1024 float4 each, 2 per thread)
#pragma unroll
    for (int i = 0; i < 2; i++) {
        reinterpret_cast<float4*>(sWg)[tid + i * 512] =
            reinterpret_cast<const float4*>(Wg)[tid + i * 512];
        reinterpret_cast<float4*>(sWb)[tid + i * 512] =
            reinterpret_cast<const float4*>(Wb)[tid + i * 512];
    }

    int rowbase = blockIdx.x * 64;
    // stage A tiles: 1024 float4 slots, 2 per thread; also clear side
#pragma unroll
    for (int p = 0; p < 2; p++) {
        int id = tid + p * 512;
        int lr = id >> 4, lc = id & 15;
        int grow = rowbase + lr;
        float4 sv = make_float4(0.f, 0.f, 0.f, 0.f);
        float4 ev = sv;
        if (grow < NN) {
            int gi4 = grow * 16 + lc;
            sv = reinterpret_cast<float4*>(g_side)[gi4];
            ev = reinterpret_cast<float4*>(g_ego)[gi4];
            reinterpret_cast<float4*>(g_side)[gi4] = make_float4(0.f, 0.f, 0.f, 0.f);
        }
        reinterpret_cast<float4*>(sS )[id] = sv;
        reinterpret_cast<float4*>(sES)[id] =
            make_float4(ev.x * sv.x, ev.y * sv.y, ev.z * sv.z, ev.w * sv.w);
    }
    __syncthreads();

    int tx = tid & 15, ty = tid >> 4;   // ty 0..31
    int c0 = tx * 4,  r0 = ty * 2;

    float accg[2][4], accb[2][4];
#pragma unroll
    for (int j = 0; j < 2; j++)
#pragma unroll
        for (int i = 0; i < 4; i++) { accg[j][i] = 0.f; accb[j][i] = 0.f; }

#pragma unroll
    for (int k4 = 0; k4 < 16; k4++) {
        float4 a[2], a2[2];
#pragma unroll
        for (int j = 0; j < 2; j++) {
            a [j] = *reinterpret_cast<const float4*>(&sS [(r0 + j) * 64 + k4 * 4]);
            a2[j] = *reinterpret_cast<const float4*>(&sES[(r0 + j) * 64 + k4 * 4]);
        }
#pragma unroll
        for (int kk = 0; kk < 4; kk++) {
            float4 wg = *reinterpret_cast<const float4*>(&sWg[(k4 * 4 + kk) * 64 + c0]);
            float4 wb = *reinterpret_cast<const float4*>(&sWb[(k4 * 4 + kk) * 64 + c0]);
#pragma unroll
            for (int j = 0; j < 2; j++) {
                float av  = (kk == 0) ? a [j].x : (kk == 1) ? a [j].y : (kk == 2) ? a [j].z : a [j].w;
                float a2v = (kk == 0) ? a2[j].x : (kk == 1) ? a2[j].y : (kk == 2) ? a2[j].z : a2[j].w;
                accg[j][0] = fmaf(av, wg.x, accg[j][0]);
                accg[j][1] = fmaf(av, wg.y, accg[j][1]);
                accg[j][2] = fmaf(av, wg.z, accg[j][2]);
                accg[j][3] = fmaf(av, wg.w, accg[j][3]);
                accb[j][0] = fmaf(a2v, wb.x, accb[j][0]);
                accb[j][1] = fmaf(a2v, wb.y, accb[j][1]);
                accb[j][2] = fmaf(a2v, wb.z, accb[j][2]);
                accb[j][3] = fmaf(a2v, wb.w, accb[j][3]);
            }
        }
    }

    float4 bgv = __ldg(reinterpret_cast<const float4*>(bg + c0));
    float4 bbv = __ldg(reinterpret_cast<const float4*>(bb + c0));
    float bga[4] = {bgv.x, bgv.y, bgv.z, bgv.w};
    float bba[4] = {bbv.x, bbv.y, bbv.z, bbv.w};

#pragma unroll
    for (int j = 0; j < 2; j++) {
        float ne[4];
        float s = 0.f;
#pragma unroll
        for (int i = 0; i < 4; i++) {
            float g = accg[j][i] + bga[i];
            float b = accb[j][i] + bba[i];
            g = (g > 0.f) ? g : 0.2f * g;
            b = (b > 0.f) ? b : 0.2f * b;
            ne[i] = g + b;
            s = fmaf(ne[i], ne[i], s);
        }
        // reduce sum of squares across the 16 tx lanes (rows live in 16-lane halves)
#pragma unroll
        for (int m = 8; m > 0; m >>= 1)
            s += __shfl_xor_sync(0xffffffffu, s, m);
        int grow = rowbase + r0 + j;
        if (grow < NN) {
            float inv = 1.f / fmaxf(sqrtf(s), 1e-12f);
            *reinterpret_cast<float4*>(&g_ego[grow * 64 + c0]) =
                make_float4(ne[0], ne[1], ne[2], ne[3]);
            *reinterpret_cast<float4*>(&out[grow * 256 + koff + c0]) =
                make_float4(ne[0] * inv, ne[1] * inv, ne[2] * inv, ne[3] * inv);
        }
    }
}

// ---------------------------------------------------------------------------
extern "C" void kernel_launch(void* const* d_in, const int* in_sizes, int n_in,
                              void* d_out, int out_size) {
    const float* ue = (const float*)d_in[0];
    const float* ie = (const float*)d_in[1];
    const float* Wg[3] = {(const float*)d_in[2],  (const float*)d_in[6],  (const float*)d_in[10]};
    const float* bg[3] = {(const float*)d_in[3],  (const float*)d_in[7],  (const float*)d_in[11]};
    const float* Wb[3] = {(const float*)d_in[4],  (const float*)d_in[8],  (const float*)d_in[12]};
    const float* bb[3] = {(const float*)d_in[5],  (const float*)d_in[9],  (const float*)d_in[13]};
    const float* vals = (const float*)d_in[14];
    const int*   rows = (const int*)d_in[15];
    const int*   cols = (const int*)d_in[16];
    float* out = (float*)d_out;

    prof_shim_kernel<<<1, 1>>>();   // shifts ncu -s 5 onto a layer_kernel launch
    init_kernel<<<(NN * 16 + 255) / 256, 256>>>(ue, ie, out);
    for (int k = 0; k < 3; k++) {
        spmm_kernel<<<(EE * 4 + 255) / 256, 256>>>(vals, rows, cols);
        layer_kernel<<<(NN + 63) / 64, 512>>>(Wg[k], bg[k], Wb[k], bb[k], out, (k + 1) * 64);
    }
}